// round 5
// baseline (speedup 1.0000x reference)
#include <cuda_runtime.h>
#include <cuda_bf16.h>

// LIF neuron scan: 2048 serial timesteps over 16384 independent neurons.
// Each thread owns one neuron; time axis is register-double-buffered with
// U=32 unroll to keep ~55 LDG outstanding per warp (HBM latency hiding).
// Streaming cache ops (__ldcs/__stcs): every byte touched exactly once.

#define LIF_T 2048
#define LIF_N 16384
#define LIF_U 32

struct LifState {
    float V;
    float Vth;
};

// Compute one chunk of U timesteps from a register buffer, storing spikes.
// All indices compile-time => buffers stay in registers.
__device__ __forceinline__ void lif_compute_chunk(
    LifState& st, const float (&bI)[LIF_U], const float (&bZ)[LIF_U],
    float* __restrict__ pO, int tbase)
{
    float V = st.V;
    float Vth = st.Vth;
#pragma unroll
    for (int u = 0; u < LIF_U; ++u) {
        const float I  = bI[u];
        const float nz = bZ[u];
        // V = V + (DT/TAU)*(I - V) + noise   (match reference op order; fma contraction)
        V = __fmaf_rn(0.05f, I - V, V) + nz;
        const bool sp = (V >= Vth);
        const float s = sp ? 1.0f : 0.0f;
        // reset on spike
        V = sp ? 0.0f : V;
        // adaptive threshold: Vth = clip(Vth + 0.1*spike, 0.5, 2.0)
        // Vth starts at 1.0 and never decreases -> lower clip is a no-op.
        const float vthp = Vth + 0.1f;
        Vth = sp ? vthp : Vth;
        Vth = fminf(Vth, 2.0f);
        __stcs(pO + (size_t)(tbase + u) * LIF_N, s);
    }
    st.V = V;
    st.Vth = Vth;
}

__device__ __forceinline__ void lif_load_chunk(
    float (&bI)[LIF_U], float (&bZ)[LIF_U],
    const float* __restrict__ pI, const float* __restrict__ pZ, int tbase)
{
#pragma unroll
    for (int u = 0; u < LIF_U; ++u) {
        bI[u] = __ldcs(pI + (size_t)(tbase + u) * LIF_N);
        bZ[u] = __ldcs(pZ + (size_t)(tbase + u) * LIF_N);
    }
}

__global__ void __launch_bounds__(128, 1)
TorchLIFNeuronGroup_kernel(const float* __restrict__ gI,
                           const float* __restrict__ gZ,
                           float* __restrict__ gOut)
{
    const int n = blockIdx.x * 128 + threadIdx.x;
    const float* pI = gI + n;
    const float* pZ = gZ + n;
    float* pO = gOut + n;

    // Two explicit register buffers; buffer selection is compile-time
    // (chunk loop advanced by 2) so nothing spills to local memory.
    float bI0[LIF_U], bZ0[LIF_U];
    float bI1[LIF_U], bZ1[LIF_U];

    LifState st;
    st.V = 0.0f;   // V_RESET
    st.Vth = 1.0f; // V_TH0

    constexpr int NCHUNK = LIF_T / LIF_U; // 64, even

    // Prologue: fill buffer 0 with chunk 0.
    lif_load_chunk(bI0, bZ0, pI, pZ, 0);

    for (int c = 0; c < NCHUNK; c += 2) {
        // Prefetch chunk c+1 into buffer 1, compute chunk c from buffer 0.
        if (c + 1 < NCHUNK) {
            lif_load_chunk(bI1, bZ1, pI, pZ, (c + 1) * LIF_U);
        }
        lif_compute_chunk(st, bI0, bZ0, pO, c * LIF_U);

        // Prefetch chunk c+2 into buffer 0, compute chunk c+1 from buffer 1.
        if (c + 2 < NCHUNK) {
            lif_load_chunk(bI0, bZ0, pI, pZ, (c + 2) * LIF_U);
        }
        if (c + 1 < NCHUNK) {
            lif_compute_chunk(st, bI1, bZ1, pO, (c + 1) * LIF_U);
        }
    }
}

extern "C" void kernel_launch(void* const* d_in, const int* in_sizes, int n_in,
                              void* d_out, int out_size)
{
    const float* input_current = (const float*)d_in[0];
    const float* noise         = (const float*)d_in[1];
    float* out                 = (float*)d_out;

    // 16384 neurons / 128 threads = 128 blocks (one per SM on 128 SMs).
    TorchLIFNeuronGroup_kernel<<<LIF_N / 128, 128>>>(input_current, noise, out);
}

// round 8
// speedup vs baseline: 2.1429x; 2.1429x over previous
#include <cuda_runtime.h>
#include <cstdint>

// LIF neuron scan: 2048 serial timesteps over 16384 independent neurons.
// R6: replace per-thread LDG (capped at ~22 outstanding/warp -> 2.7 TB/s)
// with a cp.async (LDGSTS) multi-stage shared-memory pipeline. LDGSTS has no
// outstanding-depth cap, so in-flight bytes per SM go from ~11 KB to ~128 KB
// (4 pending 32 KB stages), which should saturate HBM.
//
// Block = 128 threads = 128 neurons (blockIdx.x * 128 slab). 128 blocks,
// 1 per SM. Stage = 32 timesteps x 128 neurons x {I, noise} = 32 KB.
// 5-stage ring = 160 KB dynamic smem (needs opt-in attribute).

#define LIF_T 2048
#define LIF_N 16384
#define CHUNK 32
#define STAGES 5
#define NCHUNK (LIF_T / CHUNK)          // 64
#define BN 128                           // neurons (and threads) per block
#define STAGE_FLOATS (2 * CHUNK * BN)    // 8192 floats = 32 KB
#define SMEM_BYTES (STAGES * STAGE_FLOATS * 4)  // 160 KB

__device__ __forceinline__ void cp16(float* dst, const float4* src) {
    uint32_t s = (uint32_t)__cvta_generic_to_shared(dst);
    asm volatile("cp.async.cg.shared.global [%0], [%1], 16;\n"
                 :: "r"(s), "l"(src));
}
__device__ __forceinline__ void cp_commit() {
    asm volatile("cp.async.commit_group;\n" ::: "memory");
}
template <int N>
__device__ __forceinline__ void cp_wait() {
    asm volatile("cp.async.wait_group %0;\n" :: "n"(N) : "memory");
}

// Issue one stage's loads: CHUNK rows of 128 neurons for I and Z.
// 2048 float4 thread-ops / 128 threads = 16 cp.async per thread, 1 group.
__device__ __forceinline__ void issue_stage(
    float* __restrict__ smem, int c, int stage,
    const float4* __restrict__ gI4, const float4* __restrict__ gZ4)
{
    float* sI = smem + stage * STAGE_FLOATS;
    float* sZ = sI + CHUNK * BN;
    const int tid = threadIdx.x;
#pragma unroll
    for (int k = 0; k < 8; ++k) {
        const int idx = k * 128 + tid;       // 0..1023
        const int row = idx >> 5;            // 32 float4 per 128-neuron row
        const int col = idx & 31;
        const size_t goff = (size_t)(c * CHUNK + row) * (LIF_N / 4) + col;
        cp16(sI + row * BN + col * 4, gI4 + goff);
        cp16(sZ + row * BN + col * 4, gZ4 + goff);
    }
    cp_commit();
}

__global__ void __launch_bounds__(BN, 1)
TorchLIFNeuronGroup_kernel(const float* __restrict__ gI,
                           const float* __restrict__ gZ,
                           float* __restrict__ gOut)
{
    extern __shared__ float smem[];
    const int tid = threadIdx.x;
    const int n = blockIdx.x * BN + tid;

    // Per-block global bases (block slab offset is 512 B -> 16 B aligned).
    const float4* gI4 = (const float4*)(gI + blockIdx.x * BN);
    const float4* gZ4 = (const float4*)(gZ + blockIdx.x * BN);

    // Prologue: fill the ring.
#pragma unroll
    for (int s = 0; s < STAGES; ++s)
        issue_stage(smem, s, s, gI4, gZ4);

    float V = 0.0f;    // V_RESET
    float Vth = 1.0f;  // V_TH0

    for (int c = 0; c < NCHUNK; ++c) {
        const int stage = c % STAGES;

        // Wait until stage c's group is complete. Groups complete in order;
        // after this wait, at most `rem` newer groups may still be pending.
        const int rem = NCHUNK - 1 - c;
        if (rem >= STAGES - 1) {
            cp_wait<STAGES - 1>();
        } else {
            switch (rem) {
                case 3: cp_wait<3>(); break;
                case 2: cp_wait<2>(); break;
                case 1: cp_wait<1>(); break;
                default: cp_wait<0>(); break;
            }
        }
        __syncthreads();

        // Compute CHUNK timesteps for this thread's neuron (bit-exact R5 body).
        {
            const float* sI = smem + stage * STAGE_FLOATS + tid;
            const float* sZ = sI + CHUNK * BN;
            float* pO = gOut + (size_t)c * CHUNK * LIF_N + n;
#pragma unroll
            for (int u = 0; u < CHUNK; ++u) {
                const float I  = sI[u * BN];
                const float nz = sZ[u * BN];
                // V = V + (DT/TAU)*(I - V) + noise  (reference op order)
                V = __fmaf_rn(0.05f, I - V, V) + nz;
                const bool sp = (V >= Vth);
                __stcs(pO + (size_t)u * LIF_N, sp ? 1.0f : 0.0f);
                V = sp ? 0.0f : V;
                // Vth starts at 1.0, never decreases -> lower clip is a no-op.
                Vth = sp ? Vth + 0.1f : Vth;
                Vth = fminf(Vth, 2.0f);
            }
        }
        __syncthreads();  // all readers done before buffer reuse

        if (c + STAGES < NCHUNK)
            issue_stage(smem, c + STAGES, stage, gI4, gZ4);
    }
}

extern "C" void kernel_launch(void* const* d_in, const int* in_sizes, int n_in,
                              void* d_out, int out_size)
{
    const float* input_current = (const float*)d_in[0];
    const float* noise         = (const float*)d_in[1];
    float* out                 = (float*)d_out;

    // 160 KB dynamic smem needs the opt-in attribute (idempotent, capture-safe).
    cudaFuncSetAttribute(TorchLIFNeuronGroup_kernel,
                         cudaFuncAttributeMaxDynamicSharedMemorySize, SMEM_BYTES);

    TorchLIFNeuronGroup_kernel<<<LIF_N / BN, BN, SMEM_BYTES>>>(
        input_current, noise, out);
}